// round 1
// baseline (speedup 1.0000x reference)
#include <cuda_runtime.h>

// Maxwell viscoelastic model:
//   gamma_0 = 0
//   for t = 1..T-1: gamma_t = gamma_{t-1} + 2*dt[t-1]*(eps[t-1] - gamma_{t-1})
//   out[0] = 0 ; out[t] = 3*eps[t] - 2*gamma_t   (E_INF=1, E=2, ETA=1)
// B=16384 rows (independent), T=2048 (serial scan per row).
//
// Strategy: block of 128 rows, 128 threads (thread i owns row i).
// Time axis processed in chunks of 32. Cooperative, fully-coalesced float4
// global loads stage each chunk into padded shared memory (stride 33 ->
// conflict-free for both the staging stores and per-row scalar reads).
// sigma is written in place over the eps smem buffer, then stored back
// coalesced. Next chunk is prefetched into registers before the compute
// phase to overlap DRAM latency with the serial FMA chain.

#define RB      128                 // rows per block
#define NTHREADS 128
#define CK      32                  // timesteps per chunk
#define TT      2048
#define NCH     (TT / CK)           // 64 chunks
#define QW      (CK / 4)            // float4 per row per chunk = 8
#define F4PT    ((RB * CK) / (4 * NTHREADS))  // float4 per thread = 8

__global__ __launch_bounds__(NTHREADS, 1)
void maxwell_scan_kernel(const float* __restrict__ eps_g,
                         const float* __restrict__ dt_g,
                         float* __restrict__ out_g) {
    __shared__ float se[RB][CK + 1];
    __shared__ float sd[RB][CK + 1];

    const int tid = threadIdx.x;
    const size_t base = (size_t)blockIdx.x * RB * TT;

    float4 re[F4PT], rd[F4PT];

    // Prologue: load chunk 0 into registers.
#pragma unroll
    for (int it = 0; it < F4PT; ++it) {
        int idx = it * NTHREADS + tid;      // 0..1023
        int r = idx / QW;                   // row within block
        int q = idx % QW;                   // float4 within row
        size_t g = base + (size_t)r * TT + (size_t)q * 4;
        re[it] = *reinterpret_cast<const float4*>(eps_g + g);
        rd[it] = *reinterpret_cast<const float4*>(dt_g + g);
    }

    float gamma = 0.0f, eps_prev = 0.0f, dt_prev = 0.0f;

    for (int ch = 0; ch < NCH; ++ch) {
        // Stage registers -> shared (conflict-free with stride 33).
#pragma unroll
        for (int it = 0; it < F4PT; ++it) {
            int idx = it * NTHREADS + tid;
            int r = idx / QW, q = idx % QW;
            se[r][q * 4 + 0] = re[it].x;
            se[r][q * 4 + 1] = re[it].y;
            se[r][q * 4 + 2] = re[it].z;
            se[r][q * 4 + 3] = re[it].w;
            sd[r][q * 4 + 0] = rd[it].x;
            sd[r][q * 4 + 1] = rd[it].y;
            sd[r][q * 4 + 2] = rd[it].z;
            sd[r][q * 4 + 3] = rd[it].w;
        }

        // Prefetch next chunk into registers (overlaps compute below).
        if (ch + 1 < NCH) {
#pragma unroll
            for (int it = 0; it < F4PT; ++it) {
                int idx = it * NTHREADS + tid;
                int r = idx / QW, q = idx % QW;
                size_t g = base + (size_t)r * TT + (size_t)(ch + 1) * CK + (size_t)q * 4;
                re[it] = *reinterpret_cast<const float4*>(eps_g + g);
                rd[it] = *reinterpret_cast<const float4*>(dt_g + g);
            }
        }

        __syncthreads();

        // Compute: thread tid scans its row; sigma overwrites se in place.
#pragma unroll
        for (int j = 0; j < CK; ++j) {
            float eps = se[tid][j];
            float dt  = sd[tid][j];
            gamma = fmaf(dt_prev + dt_prev, eps_prev - gamma, gamma);
            float sig = fmaf(2.0f, eps - gamma, eps);
            if (ch == 0 && j == 0) sig = 0.0f;   // out[0] = 0
            se[tid][j] = sig;
            eps_prev = eps;
            dt_prev  = dt;
        }

        __syncthreads();

        // Coalesced float4 store of sigma.
#pragma unroll
        for (int it = 0; it < F4PT; ++it) {
            int idx = it * NTHREADS + tid;
            int r = idx / QW, q = idx % QW;
            float4 v;
            v.x = se[r][q * 4 + 0];
            v.y = se[r][q * 4 + 1];
            v.z = se[r][q * 4 + 2];
            v.w = se[r][q * 4 + 3];
            *reinterpret_cast<float4*>(out_g + base + (size_t)r * TT +
                                       (size_t)ch * CK + (size_t)q * 4) = v;
        }

        __syncthreads();
    }
}

extern "C" void kernel_launch(void* const* d_in, const int* in_sizes, int n_in,
                              void* d_out, int out_size) {
    const float* strains = (const float*)d_in[0];
    const float* dts     = (const float*)d_in[1];
    float* out           = (float*)d_out;

    const int B = 16384;
    maxwell_scan_kernel<<<B / RB, NTHREADS>>>(strains, dts, out);
}

// round 2
// speedup vs baseline: 1.3701x; 1.3701x over previous
#include <cuda_runtime.h>

// Maxwell viscoelastic model, warp-parallel affine-scan formulation.
//   gamma_0 = 0
//   gamma_t = gamma_{t-1} + 2*dt_{t-1}*(eps_{t-1} - gamma_{t-1})   (t >= 1)
//   out_0 = 0 ; out_t = 3*eps_t - 2*gamma_t
//
// gamma recurrence is affine: gamma_{t+1} = A_t*gamma_t + B_t with
//   A_t = 1 - 2*dt_t,  B_t = 2*dt_t*eps_t   (map "consuming" element t).
// A warp processes 128 consecutive timesteps of ONE row per iteration:
//   - each lane loads float4 (elements 4j..4j+3), composes its 4 maps,
//   - 5-round Kogge-Stone shuffle scan composes maps across lanes,
//   - exclusive prefix gives gamma at each lane's first element,
//   - per-lane serial apply emits 4 sigmas, stored as one coalesced float4.
// No shared memory, no __syncthreads, 16384 warps of parallelism.

#define TT 2048
#define ELEMS_PER_ITER 128            // per warp per iteration
#define NITER (TT / ELEMS_PER_ITER)   // 16
#define WARPS_PER_BLOCK 8
#define NTHREADS (WARPS_PER_BLOCK * 32)

__global__ __launch_bounds__(NTHREADS, 4)
void maxwell_warp_scan(const float* __restrict__ eps_g,
                       const float* __restrict__ dt_g,
                       float* __restrict__ out_g) {
    const int lane = threadIdx.x & 31;
    const int warp = threadIdx.x >> 5;
    const int row  = blockIdx.x * WARPS_PER_BLOCK + warp;
    const size_t base = (size_t)row * TT;

    const float4* eps4 = reinterpret_cast<const float4*>(eps_g + base);
    const float4* dt4  = reinterpret_cast<const float4*>(dt_g  + base);
    float4*       out4 = reinterpret_cast<float4*>(out_g + base);

    float gamma_in = 0.0f;

    // Prefetch iteration 0.
    float4 e = eps4[lane];
    float4 d = dt4[lane];

#pragma unroll 1
    for (int it = 0; it < NITER; ++it) {
        // Prefetch next iteration (overlaps the shuffle-scan chain below).
        float4 en, dn;
        if (it + 1 < NITER) {
            en = eps4[(it + 1) * 32 + lane];
            dn = dt4[(it + 1) * 32 + lane];
        } else {
            en = e; dn = d;
        }

        // Per-element maps; compose lane-local aggregate L = m3.m2.m1.m0.
        const float td0 = d.x + d.x, td1 = d.y + d.y,
                    td2 = d.z + d.z, td3 = d.w + d.w;
        float A = 1.0f - td0;
        float B = td0 * e.x;
        {
            const float A1 = 1.0f - td1, B1 = td1 * e.y;
            B = fmaf(A1, B, B1); A = A1 * A;
            const float A2 = 1.0f - td2, B2 = td2 * e.z;
            B = fmaf(A2, B, B2); A = A2 * A;
            const float A3 = 1.0f - td3, B3 = td3 * e.w;
            B = fmaf(A3, B, B3); A = A3 * A;
        }

        // Inclusive Kogge-Stone scan of affine maps across the warp.
        float SA = A, SB = B;
#pragma unroll
        for (int dstep = 1; dstep < 32; dstep <<= 1) {
            const float pA = __shfl_up_sync(0xffffffffu, SA, dstep);
            const float pB = __shfl_up_sync(0xffffffffu, SB, dstep);
            if (lane >= dstep) {
                SB = fmaf(SA, pB, SB);
                SA = SA * pA;
            }
        }

        // Exclusive prefix for this lane (identity on lane 0).
        float EA = __shfl_up_sync(0xffffffffu, SA, 1);
        float EB = __shfl_up_sync(0xffffffffu, SB, 1);
        if (lane == 0) { EA = 1.0f; EB = 0.0f; }

        // gamma at this lane's first element.
        float g = fmaf(EA, gamma_in, EB);

        // Serial apply: sigma_t = eps_t + 2*(eps_t - gamma_t), then advance gamma.
        float4 s;
        s.x = fmaf(2.0f, e.x - g, e.x);
        g   = fmaf(td0,  e.x - g, g);
        s.y = fmaf(2.0f, e.y - g, e.y);
        g   = fmaf(td1,  e.y - g, g);
        s.z = fmaf(2.0f, e.z - g, e.z);
        g   = fmaf(td2,  e.z - g, g);
        s.w = fmaf(2.0f, e.w - g, e.w);

        if (it == 0 && lane == 0) s.x = 0.0f;   // out[0] = 0

        out4[it * 32 + lane] = s;

        // Warp-wide carry: full 128-element map from lane 31.
        const float CA = __shfl_sync(0xffffffffu, SA, 31);
        const float CB = __shfl_sync(0xffffffffu, SB, 31);
        gamma_in = fmaf(CA, gamma_in, CB);

        e = en; d = dn;
    }
}

extern "C" void kernel_launch(void* const* d_in, const int* in_sizes, int n_in,
                              void* d_out, int out_size) {
    const float* strains = (const float*)d_in[0];
    const float* dts     = (const float*)d_in[1];
    float* out           = (float*)d_out;

    const int B = 16384;
    maxwell_warp_scan<<<B / WARPS_PER_BLOCK, NTHREADS>>>(strains, dts, out);
}

// round 3
// speedup vs baseline: 1.4504x; 1.0586x over previous
#include <cuda_runtime.h>

// Maxwell viscoelastic model, warp-parallel affine-scan, 256 elems/warp-iter.
//   gamma_{t+1} = A_t*gamma_t + B_t,  A_t = 1-2*dt_t, B_t = 2*dt_t*eps_t
//   out_0 = 0 ; out_t = 3*eps_t - 2*gamma_t = eps_t + 2*(eps_t - gamma_t)
//
// Each lane owns 8 CONTIGUOUS timesteps (2x float4); a 5-round Kogge-Stone
// shuffle scan composes the 32 lane-local affine maps, so the shuffle cost
// is amortized over 256 elements instead of 128. Streaming cache hints
// (__ldcs/__stcs) since every byte is touched exactly once.

#define TT   2048
#define EPL  8                         // elements per lane
#define EPI  (EPL * 32)                // 256 per warp-iteration
#define NITER (TT / EPI)               // 8
#define WARPS_PER_BLOCK 8
#define NTHREADS (WARPS_PER_BLOCK * 32)

__global__ __launch_bounds__(NTHREADS, 4)
void maxwell_warp_scan256(const float* __restrict__ eps_g,
                          const float* __restrict__ dt_g,
                          float* __restrict__ out_g) {
    const int lane = threadIdx.x & 31;
    const int warp = threadIdx.x >> 5;
    const int row  = blockIdx.x * WARPS_PER_BLOCK + warp;
    const size_t base = (size_t)row * TT;

    const float4* eps4 = reinterpret_cast<const float4*>(eps_g + base);
    const float4* dt4  = reinterpret_cast<const float4*>(dt_g  + base);
    float4*       out4 = reinterpret_cast<float4*>(out_g + base);

    float gamma_in = 0.0f;

    // float4 index of this lane's first quad within an iteration block.
    // Iteration 'it' covers float4 indices [it*64, it*64+64).
    const int q0 = lane * 2;

    // Prefetch iteration 0.
    float4 e0 = __ldcs(&eps4[q0]);
    float4 e1 = __ldcs(&eps4[q0 + 1]);
    float4 d0 = __ldcs(&dt4[q0]);
    float4 d1 = __ldcs(&dt4[q0 + 1]);

#pragma unroll 1
    for (int it = 0; it < NITER; ++it) {
        // Prefetch next iteration (in flight across the shuffle chain).
        float4 e0n, e1n, d0n, d1n;
        if (it + 1 < NITER) {
            const int qn = (it + 1) * 64 + q0;
            e0n = __ldcs(&eps4[qn]);
            e1n = __ldcs(&eps4[qn + 1]);
            d0n = __ldcs(&dt4[qn]);
            d1n = __ldcs(&dt4[qn + 1]);
        }

        const float ee[EPL] = {e0.x, e0.y, e0.z, e0.w, e1.x, e1.y, e1.z, e1.w};
        const float dd[EPL] = {d0.x, d0.y, d0.z, d0.w, d1.x, d1.y, d1.z, d1.w};

        float td[EPL];
#pragma unroll
        for (int k = 0; k < EPL; ++k) td[k] = dd[k] + dd[k];

        // Lane-local compose of 8 affine maps: (A,B) = m7∘...∘m0.
        float A = 1.0f - td[0];
        float B = td[0] * ee[0];
#pragma unroll
        for (int k = 1; k < EPL; ++k) {
            const float Ak = 1.0f - td[k];
            const float Bk = td[k] * ee[k];
            B = fmaf(Ak, B, Bk);
            A = Ak * A;
        }

        // Inclusive Kogge-Stone scan of affine maps across the warp.
        float SA = A, SB = B;
#pragma unroll
        for (int dstep = 1; dstep < 32; dstep <<= 1) {
            const float pA = __shfl_up_sync(0xffffffffu, SA, dstep);
            const float pB = __shfl_up_sync(0xffffffffu, SB, dstep);
            if (lane >= dstep) {
                SB = fmaf(SA, pB, SB);
                SA = SA * pA;
            }
        }

        // Exclusive prefix (identity on lane 0).
        float EA = __shfl_up_sync(0xffffffffu, SA, 1);
        float EB = __shfl_up_sync(0xffffffffu, SB, 1);
        if (lane == 0) { EA = 1.0f; EB = 0.0f; }

        // gamma entering this lane's first element.
        float g = fmaf(EA, gamma_in, EB);

        // Serial apply: t = eps - gamma; sigma = eps + 2t; gamma += 2dt*t.
        float ss[EPL];
#pragma unroll
        for (int k = 0; k < EPL; ++k) {
            const float t = ee[k] - g;
            ss[k] = fmaf(2.0f, t, ee[k]);
            g = fmaf(td[k], t, g);
        }

        if (it == 0 && lane == 0) ss[0] = 0.0f;   // out[0] = 0

        float4 s0 = make_float4(ss[0], ss[1], ss[2], ss[3]);
        float4 s1 = make_float4(ss[4], ss[5], ss[6], ss[7]);
        const int qo = it * 64 + q0;
        __stcs(&out4[qo],     s0);
        __stcs(&out4[qo + 1], s1);

        // Warp-wide carry from lane 31's inclusive map.
        const float CA = __shfl_sync(0xffffffffu, SA, 31);
        const float CB = __shfl_sync(0xffffffffu, SB, 31);
        gamma_in = fmaf(CA, gamma_in, CB);

        if (it + 1 < NITER) { e0 = e0n; e1 = e1n; d0 = d0n; d1 = d1n; }
    }
}

extern "C" void kernel_launch(void* const* d_in, const int* in_sizes, int n_in,
                              void* d_out, int out_size) {
    const float* strains = (const float*)d_in[0];
    const float* dts     = (const float*)d_in[1];
    float* out           = (float*)d_out;

    const int B = 16384;
    maxwell_warp_scan256<<<B / WARPS_PER_BLOCK, NTHREADS>>>(strains, dts, out);
}